// round 1
// baseline (speedup 1.0000x reference)
#include <cuda_runtime.h>
#include <math.h>

#define B_  32
#define H_  512
#define W_  512
#define DEG 0.017453292519943295f

// Per-batch params: M[9], gamma, Mc[9], apply, cx, cy, cwHalf, chHalf = 24 floats, pad to 32
__device__ float g_params[B_ * 32];

__device__ __forceinline__ void mat3_mul(const float* A, const float* Bm, float* C) {
#pragma unroll
    for (int i = 0; i < 3; i++)
#pragma unroll
        for (int j = 0; j < 3; j++) {
            float s = 0.f;
#pragma unroll
            for (int k = 0; k < 3; k++) s += A[i * 3 + k] * Bm[k * 3 + j];
            C[i * 3 + j] = s;
        }
}

__global__ void param_kernel(const float* __restrict__ geom_u,
                             const float* __restrict__ color_u,
                             const float* __restrict__ cutout_u) {
    int b = threadIdx.x;
    if (b >= B_) return;

    // ---- geometry ----
    const float* g = geom_u + b * 8;
    float flip = g[0] > 0.5f ? -1.f : 1.f;
    float tilt = (g[1] * 2.f - 1.f) * (15.f * DEG);
    float pan  = (g[2] * 2.f - 1.f) * (15.f * DEG);
    float rot  = (g[3] * 2.f - 1.f) * (15.f * DEG);
    float sc   = 1.f + (g[4] * 2.f - 1.f) * 0.1f;
    float tx   = (g[5] * 2.f - 1.f) * 0.2f;
    float ty   = (g[6] * 2.f - 1.f) * 0.2f;

    float F[9]  = {flip, 0, 0, 0, 1, 0, 0, 0, 1};
    float ct = cosf(tilt), st = sinf(tilt);
    float Rx[9] = {1, 0, 0, 0, ct, -st, 0, st, ct};
    float cp = cosf(pan), sp = sinf(pan);
    float Ry[9] = {cp, 0, sp, 0, 1, 0, -sp, 0, cp};
    float cr = cosf(rot), sr = sinf(rot);
    float RS[9] = {sc * cr, -sc * sr, 0, sc * sr, sc * cr, 0, 0, 0, 1};
    float T[9]  = {1, 0, tx, 0, 1, ty, 0, 0, 1};

    float t0[9], t1[9], t2[9], M[9];
    mat3_mul(Ry, F, t0);     // Ry@F
    mat3_mul(Rx, t0, t1);    // Rx@Ry@F
    mat3_mul(RS, t1, t2);    // RS@...
    mat3_mul(T, t2, M);      // T@...

    // ---- color ----
    const float* c = color_u + b * 4;
    float theta = (c[0] * 2.f - 1.f) * (10.f * DEG);
    float cth = cosf(theta), sth = sinf(theta);
    const float a = 0.5773502691896258f; // 1/sqrt(3)
    float K[9] = {0, -a, a, a, 0, -a, -a, a, 0};
    float Rh[9];
#pragma unroll
    for (int i = 0; i < 3; i++)
#pragma unroll
        for (int j = 0; j < 3; j++)
            Rh[i * 3 + j] = cth * (i == j ? 1.f : 0.f) + sth * K[i * 3 + j] +
                            (1.f - cth) * (1.f / 3.f);
    float sat = 1.f + (c[1] * 2.f - 1.f) * 0.4f;
    const float lum[3] = {0.299f, 0.587f, 0.114f};
    float Sm[9];
#pragma unroll
    for (int i = 0; i < 3; i++)
#pragma unroll
        for (int j = 0; j < 3; j++)
            Sm[i * 3 + j] = sat * (i == j ? 1.f : 0.f) + (1.f - sat) * lum[j];
    float bright = 1.f + (c[2] * 2.f - 1.f) * 0.1f;
    float Mc[9];
    mat3_mul(Sm, Rh, Mc);
#pragma unroll
    for (int i = 0; i < 9; i++) Mc[i] *= bright;
    float gamma = 1.f + (c[3] * 2.f - 1.f) * 0.2f;

    // ---- cutout ----
    const float* cu = cutout_u + b * 5;
    float apply  = (cu[0] < 0.5f) ? 1.f : 0.f;
    float cx     = cu[1];
    float cy     = cu[2];
    float cwHalf = (0.3f + 0.2f * cu[3]) * 0.5f;
    float chHalf = (0.3f + 0.2f * cu[4]) * 0.5f;

    float* p = g_params + b * 32;
#pragma unroll
    for (int i = 0; i < 9; i++) p[i] = M[i];
    p[9] = gamma;
#pragma unroll
    for (int i = 0; i < 9; i++) p[10 + i] = Mc[i];
    p[19] = apply;
    p[20] = cx;
    p[21] = cy;
    p[22] = cwHalf;
    p[23] = chHalf;
}

__global__ __launch_bounds__(512) void augment_kernel(
    const float* __restrict__ images, float* __restrict__ out) {
    // one block per (b, row); 512 threads = one output row
    int blk = blockIdx.x;
    int b = blk >> 9;          // blk / 512
    int i = blk & (H_ - 1);    // row
    int j = threadIdx.x;       // col

    __shared__ float sp[24];
    if (threadIdx.x < 24) sp[threadIdx.x] = g_params[b * 32 + threadIdx.x];
    __syncthreads();

    const float inv511 = 1.f / 511.f;
    float x = (float)j * (2.f * inv511) - 1.f;
    float y = (float)i * (2.f * inv511) - 1.f;

    // warp
    float sx = sp[0] * x + sp[1] * y + sp[2];
    float sy = sp[3] * x + sp[4] * y + sp[5];
    float sz = sp[6] * x + sp[7] * y + sp[8];
    float inv = 1.f / sz;
    float u = sx * inv, v = sy * inv;
    float px = (u + 1.f) * 255.5f;
    float py = (v + 1.f) * 255.5f;

    bool valid = (px >= 0.f) & (px <= 511.f) & (py >= 0.f) & (py <= 511.f);

    float fx0 = floorf(px);
    fx0 = fminf(fmaxf(fx0, 0.f), 511.f);
    float fy0 = floorf(py);
    fy0 = fminf(fmaxf(fy0, 0.f), 511.f);
    float wx = px - fx0;
    float wy = py - fy0;
    int x0 = (int)fx0, y0 = (int)fy0;
    int x1 = min(x0 + 1, W_ - 1);
    int y1 = min(y0 + 1, H_ - 1);

    const float* img = images + (size_t)b * (H_ * W_ * 3);
    const float* p00 = img + (y0 * W_ + x0) * 3;
    const float* p01 = img + (y0 * W_ + x1) * 3;
    const float* p10 = img + (y1 * W_ + x0) * 3;
    const float* p11 = img + (y1 * W_ + x1) * 3;

    float w00 = (1.f - wx) * (1.f - wy);
    float w01 = wx * (1.f - wy);
    float w10 = (1.f - wx) * wy;
    float w11 = wx * wy;
    float vm = valid ? 1.f : 0.f;

    float gamma = sp[9];
    float r[3];
#pragma unroll
    for (int ch = 0; ch < 3; ch++) {
        float s = __ldg(p00 + ch) * w00 + __ldg(p01 + ch) * w01 +
                  __ldg(p10 + ch) * w10 + __ldg(p11 + ch) * w11;
        s *= vm;
        // gamma: clip then pow
        s = fminf(fmaxf(s, 0.f), 1.f);
        s = exp2f(gamma * __log2f(s)); // 0 -> exp2(-inf) = 0, matches 0^g
        r[ch] = s;
    }

    // color matrix (row d of Mc dotted with channel vector), clip
    float o0 = sp[10] * r[0] + sp[11] * r[1] + sp[12] * r[2];
    float o1 = sp[13] * r[0] + sp[14] * r[1] + sp[15] * r[2];
    float o2 = sp[16] * r[0] + sp[17] * r[1] + sp[18] * r[2];
    o0 = fminf(fmaxf(o0, 0.f), 1.f);
    o1 = fminf(fmaxf(o1, 0.f), 1.f);
    o2 = fminf(fmaxf(o2, 0.f), 1.f);

    // cutout
    float gx = (float)j * inv511;
    float gy = (float)i * inv511;
    bool cut = (sp[19] != 0.f) & (fabsf(gx - sp[20]) < sp[22]) &
               (fabsf(gy - sp[21]) < sp[23]);
    if (cut) { o0 = 0.f; o1 = 0.f; o2 = 0.f; }

    float* op = out + ((size_t)blk * W_ + j) * 3;
    op[0] = o0;
    op[1] = o1;
    op[2] = o2;
}

extern "C" void kernel_launch(void* const* d_in, const int* in_sizes, int n_in,
                              void* d_out, int out_size) {
    const float* images   = (const float*)d_in[0];
    const float* geom_u   = (const float*)d_in[1];
    const float* color_u  = (const float*)d_in[2];
    const float* cutout_u = (const float*)d_in[3];
    float* out = (float*)d_out;

    param_kernel<<<1, 32>>>(geom_u, color_u, cutout_u);
    augment_kernel<<<B_ * H_, W_>>>(images, out);
}